// round 13
// baseline (speedup 1.0000x reference)
#include <cuda_runtime.h>
#include <cuda_bf16.h>
#include <cstdint>

#define NB 8
#define NT 1024
#define ND 512
#define NH 8
#define NDH 64
#define NSPOS 2047
#define ATT_SCALE 0.125f

typedef unsigned long long ull;

// ---------------- scratch (device globals; no allocs allowed) ----------------
__device__ float g_q[NB*NH*NT*NDH];
__device__ float g_k[NB*NH*NT*NDH];
__device__ float g_v[NB*NH*NT*NDH];
__device__ float g_p[NH*NSPOS*NDH];
__device__ float g_ao[NB*NT*ND];
__device__ float g_uk[NB*NH*NT];
__device__ float g_vp[NH*NSPOS];
__device__ float g_posu[64*1024*1024];   // Uc[bh][t][s], shifted pos scores
__device__ __nv_bfloat16 g_xh[NB*NT*ND],  g_xl[NB*NT*ND];
__device__ __nv_bfloat16 g_peh[2048*ND],  g_pel[2048*ND];
__device__ __nv_bfloat16 g_wth[5*ND*ND],  g_wtl[5*ND*ND];
__device__ __nv_bfloat16 g_aoh[NB*NT*ND], g_aol[NB*NT*ND];

// ---------------- scalar f32x2 helpers (attention) ----------------
__device__ __forceinline__ void ffma2(ull &d, ull a, ull b) {
    asm("fma.rn.f32x2 %0, %1, %2, %0;" : "+l"(d) : "l"(a), "l"(b));
}
__device__ __forceinline__ void fmul2(ull &d, ull a) {
    asm("mul.rn.f32x2 %0, %0, %1;" : "+l"(d) : "l"(a));
}
__device__ __forceinline__ ull fdup(float x) {
    ull r; asm("mov.b64 %0, {%1, %1};" : "=l"(r) : "f"(x)); return r;
}
__device__ __forceinline__ float2 unpk(ull v) {
    float2 f; asm("mov.b64 {%0, %1}, %2;" : "=f"(f.x), "=f"(f.y) : "l"(v)); return f;
}

// ---------------- mma.sync / ldmatrix / cp.async helpers ----------------
__device__ __forceinline__ uint32_t smem_u32(const void* p) {
    uint32_t a;
    asm("{ .reg .u64 t; cvta.to.shared.u64 t, %1; cvt.u32.u64 %0, t; }" : "=r"(a) : "l"(p));
    return a;
}
#define LDSM4(r, addr) \
    asm volatile("ldmatrix.sync.aligned.m8n8.x4.shared.b16 {%0,%1,%2,%3}, [%4];" \
        : "=r"((r)[0]), "=r"((r)[1]), "=r"((r)[2]), "=r"((r)[3]) : "r"(addr))
#define MMA16816(c, a, b0, b1) \
    asm volatile("mma.sync.aligned.m16n8k16.row.col.f32.bf16.bf16.f32 " \
        "{%0,%1,%2,%3}, {%4,%5,%6,%7}, {%8,%9}, {%0,%1,%2,%3};" \
        : "+f"((c)[0]), "+f"((c)[1]), "+f"((c)[2]), "+f"((c)[3]) \
        : "r"((a)[0]), "r"((a)[1]), "r"((a)[2]), "r"((a)[3]), "r"(b0), "r"(b1))
__device__ __forceinline__ void cpa16(uint32_t dst, const void* src, int sz) {
    asm volatile("cp.async.cg.shared.global [%0], [%1], 16, %2;"
                 :: "r"(dst), "l"(src), "r"(sz) : "memory");
}
__device__ __forceinline__ void cpa_commit() {
    asm volatile("cp.async.commit_group;" ::: "memory");
}
__device__ __forceinline__ void cpa_wait0() {
    asm volatile("cp.async.wait_group 0;" ::: "memory");
}

// split a float4 into hi/lo bf16 quads stored as two bf162 each
__device__ __forceinline__ void split4(float4 v, __nv_bfloat16* hdst, __nv_bfloat16* ldst) {
    __nv_bfloat16 h0 = __float2bfloat16(v.x), h1 = __float2bfloat16(v.y);
    __nv_bfloat16 h2 = __float2bfloat16(v.z), h3 = __float2bfloat16(v.w);
    ((__nv_bfloat162*)hdst)[0] = __nv_bfloat162(h0, h1);
    ((__nv_bfloat162*)hdst)[1] = __nv_bfloat162(h2, h3);
    ((__nv_bfloat162*)ldst)[0] = __nv_bfloat162(
        __float2bfloat16(v.x - __bfloat162float(h0)),
        __float2bfloat16(v.y - __bfloat162float(h1)));
    ((__nv_bfloat162*)ldst)[1] = __nv_bfloat162(
        __float2bfloat16(v.z - __bfloat162float(h2)),
        __float2bfloat16(v.w - __bfloat162float(h3)));
}

// ---------------- split-precision convert kernels ----------------
__global__ __launch_bounds__(256)
void split_k(const float* __restrict__ s, __nv_bfloat16* __restrict__ h,
             __nv_bfloat16* __restrict__ l, int n4)
{
    int i = blockIdx.x * 256 + threadIdx.x;
    if (i >= n4) return;
    float4 v = ((const float4*)s)[i];
    split4(v, h + i * 4, l + i * 4);
}

// Transpose + split the 5 weight matrices: wt[z][n][k] = W_z[k][n]
__global__ __launch_bounds__(256)
void wsplit_k(const float* __restrict__ W0, const float* __restrict__ W1,
              const float* __restrict__ W2, const float* __restrict__ W3,
              const float* __restrict__ W4,
              __nv_bfloat16* __restrict__ th, __nv_bfloat16* __restrict__ tl)
{
    const float* W;
    switch (blockIdx.z) {
        case 0: W = W0; break;
        case 1: W = W1; break;
        case 2: W = W2; break;
        case 3: W = W3; break;
        default: W = W4; break;
    }
    __shared__ float t[32][33];
    int tx = threadIdx.x & 31, ty = threadIdx.x >> 5;
    int n0 = blockIdx.x * 32, k0 = blockIdx.y * 32;
#pragma unroll
    for (int ph = 0; ph < 4; ph++)
        t[ty + ph * 8][tx] = W[(size_t)(k0 + ty + ph * 8) * ND + n0 + tx];
    __syncthreads();
    size_t base = (size_t)blockIdx.z * ND * ND;
#pragma unroll
    for (int ph = 0; ph < 4; ph++) {
        int n = n0 + ty + ph * 8, k = k0 + tx;
        float v = t[tx][ty + ph * 8];
        __nv_bfloat16 hh = __float2bfloat16(v);
        __nv_bfloat16 ll = __float2bfloat16(v - __bfloat162float(hh));
        th[base + (size_t)n * ND + k] = hh;
        tl[base + (size_t)n * ND + k] = ll;
    }
}

// ---------------------------------------------------------------------------
// mma.sync split-bf16 GEMM (unchanged from R11).
// ---------------------------------------------------------------------------
#define MT_AH 0
#define MT_AL 10240
#define MT_BH 20480
#define MT_BL 30720
#define MT_BUF 40960
#define MT_SMEM 81920

template<int MODE>
__device__ __forceinline__
void mmagemm_body(const __nv_bfloat16* __restrict__ Ah, const __nv_bfloat16* __restrict__ Al,
                  const __nv_bfloat16* __restrict__ Bh, const __nv_bfloat16* __restrict__ Bl,
                  const float* __restrict__ bias, float* __restrict__ C,
                  int M, int row0, int col0, char* smraw)
{
    const int tid  = threadIdx.x;
    const int lane = tid & 31;
    const int wid  = tid >> 5;
    const int warp_m = wid >> 2;
    const int warp_n = wid & 3;
    const uint32_t smb = smem_u32(smraw);

    const int ldrow = tid >> 1;
    const int ldc8  = (tid & 1) * 16;
    const bool okA  = (row0 + ldrow) < M;
    const size_t agoff = (size_t)(row0 + ldrow) * ND;
    const size_t bgoff = (size_t)(col0 + ldrow) * ND;
    const uint32_t srow = (uint32_t)ldrow * 40;
    const int szA = okA ? 16 : 0;

    float acc[4][4][4];
#pragma unroll
    for (int mi = 0; mi < 4; mi++)
#pragma unroll
        for (int ni = 0; ni < 4; ni++)
#pragma unroll
            for (int e = 0; e < 4; e++) acc[mi][ni][e] = 0.f;

    const int a_row = warp_m * 64 + (lane & 7) + ((lane >> 3) & 1) * 8;
    const int b_row = warp_n * 32 + (lane & 7) + ((lane >> 3) & 1) * 8;
    const int lm_k  = (lane >> 4) * 8;

    auto load_tile = [&](int k0, int buf) {
        uint32_t sb = smb + buf * MT_BUF;
#pragma unroll
        for (int c = 0; c < 2; c++) {
            int col = ldc8 + c * 8;
            uint32_t so = (srow + col) * 2;
            cpa16(sb + MT_AH + so, Ah + agoff + k0 + col, szA);
            cpa16(sb + MT_AL + so, Al + agoff + k0 + col, szA);
            cpa16(sb + MT_BH + so, Bh + bgoff + k0 + col, 16);
            cpa16(sb + MT_BL + so, Bl + bgoff + k0 + col, 16);
        }
    };

    load_tile(0, 0);
    cpa_commit();

    int buf = 0;
    for (int it = 0; it < 16; it++) {
        cpa_wait0();
        __syncthreads();
        if (it < 15) {
            load_tile((it + 1) * 32, buf ^ 1);
            cpa_commit();
        }
        const uint32_t sb = smb + buf * MT_BUF;
#pragma unroll
        for (int ks = 0; ks < 2; ks++) {
            const int kofs = ks * 16 + lm_k;
            uint32_t bh[2][4], bl[2][4];
#pragma unroll
            for (int p = 0; p < 2; p++) {
                uint32_t off = (uint32_t)((b_row + p * 16) * 40 + kofs) * 2;
                LDSM4(bh[p], sb + MT_BH + off);
                LDSM4(bl[p], sb + MT_BL + off);
            }
#pragma unroll
            for (int mi = 0; mi < 4; mi++) {
                uint32_t ah[4], al[4];
                uint32_t off = (uint32_t)((a_row + mi * 16) * 40 + kofs) * 2;
                LDSM4(ah, sb + MT_AH + off);
                LDSM4(al, sb + MT_AL + off);
#pragma unroll
                for (int ni = 0; ni < 4; ni++) {
                    const int p = ni >> 1, hi = ni & 1;
                    MMA16816(acc[mi][ni], ah, bh[p][hi], bh[p][hi + 2]);
                    MMA16816(acc[mi][ni], ah, bl[p][hi], bl[p][hi + 2]);
                    MMA16816(acc[mi][ni], al, bh[p][hi], bh[p][hi + 2]);
                }
            }
        }
        buf ^= 1;
    }

#pragma unroll
    for (int mi = 0; mi < 4; mi++) {
        const int r0 = row0 + warp_m * 64 + mi * 16 + (lane >> 2);
#pragma unroll
        for (int ni = 0; ni < 4; ni++) {
            const int col = col0 + warp_n * 32 + ni * 8 + (lane & 3) * 2;
            const float b0 = bias ? bias[col] : 0.f;
            const float b1 = bias ? bias[col + 1] : 0.f;
#pragma unroll
            for (int half = 0; half < 2; half++) {
                const int m = r0 + half * 8;
                if (m >= M) continue;
                float2 o;
                o.x = acc[mi][ni][half * 2 + 0] + b0;
                o.y = acc[mi][ni][half * 2 + 1] + b1;
                if (MODE == 0) {
                    *(float2*)(C + (size_t)m * ND + col) = o;
                } else if (MODE == 1) {
                    int b = m >> 10, t = m & 1023;
                    int h = col >> 6, d = col & 63;
                    *(float2*)(C + ((size_t)((b << 3) + h) * NT + t) * NDH + d) = o;
                } else {
                    int h = col >> 6, d = col & 63;
                    *(float2*)(C + ((size_t)h * NSPOS + m) * NDH + d) = o;
                }
            }
        }
    }
}

template<int MODE>
__global__ __launch_bounds__(256, 2)
void mmagemm_k(const __nv_bfloat16* __restrict__ Ah, const __nv_bfloat16* __restrict__ Al,
               const __nv_bfloat16* __restrict__ Bh, const __nv_bfloat16* __restrict__ Bl,
               const float* __restrict__ bias, float* __restrict__ C, int M)
{
    extern __shared__ char smraw[];
    mmagemm_body<MODE>(Ah, Al, Bh, Bl, bias, C, M,
                       blockIdx.x << 7, blockIdx.y << 7, smraw);
}

__global__ __launch_bounds__(256, 2)
void mmagemm_fused_k(const __nv_bfloat16* __restrict__ xh, const __nv_bfloat16* __restrict__ xl,
                     const __nv_bfloat16* __restrict__ peh, const __nv_bfloat16* __restrict__ pel,
                     const __nv_bfloat16* __restrict__ wth, const __nv_bfloat16* __restrict__ wtl,
                     const float* __restrict__ bq, const float* __restrict__ bk,
                     const float* __restrict__ bv,
                     float* __restrict__ Cq, float* __restrict__ Ck,
                     float* __restrict__ Cv, float* __restrict__ Cp)
{
    extern __shared__ char smraw[];
    const int z = blockIdx.z;
    const size_t WSZ = (size_t)ND * ND;
    if (z == 3) {
        if (blockIdx.x >= 16) return;
        mmagemm_body<2>(peh, pel, wth + 3 * WSZ, wtl + 3 * WSZ, nullptr, Cp, NSPOS,
                        blockIdx.x << 7, blockIdx.y << 7, smraw);
    } else {
        const float* bias = (z == 0) ? bq : (z == 1) ? bk : bv;
        float* C = (z == 0) ? Cq : (z == 1) ? Ck : Cv;
        mmagemm_body<1>(xh, xl, wth + z * WSZ, wtl + z * WSZ, bias, C, NB * NT,
                        blockIdx.x << 7, blockIdx.y << 7, smraw);
    }
}

// ---------------------------------------------------------------------------
// Precompute uk / vp rank-1 terms.
// ---------------------------------------------------------------------------
#define NUKROWS (NB*NH*NT)
#define NVPROWS (NH*NSPOS)
__global__ __launch_bounds__(256)
void biasdot_k(const float* __restrict__ k, const float* __restrict__ p,
               const float* __restrict__ pbu, const float* __restrict__ pbv,
               float* __restrict__ uk, float* __restrict__ vp)
{
    int w = (blockIdx.x * 256 + threadIdx.x) >> 5;
    int lane = threadIdx.x & 31;
    if (w < NUKROWS) {
        int h = (w >> 10) & 7;
        float2 a = *(const float2*)(k + (size_t)w * NDH + lane * 2);
        float2 u = *(const float2*)(pbu + h * NDH + lane * 2);
        float s = a.x * u.x + a.y * u.y;
#pragma unroll
        for (int off = 16; off >= 1; off >>= 1)
            s += __shfl_xor_sync(0xffffffffu, s, off);
        if (lane == 0) uk[w] = s;
    } else if (w < NUKROWS + NVPROWS) {
        int r = w - NUKROWS;
        float2 a = *(const float2*)(p + (size_t)r * NDH + lane * 2);
        int h = r / NSPOS;
        float2 u = *(const float2*)(pbv + h * NDH + lane * 2);
        float s = a.x * u.x + a.y * u.y;
#pragma unroll
        for (int off = 16; off >= 1; off >>= 1)
            s += __shfl_xor_sync(0xffffffffu, s, off);
        if (lane == 0) vp[r] = s;
    }
}

// ---------------------------------------------------------------------------
// posu_k: Uc[bh][t][s] = q[bh,t] . p[h, 1023+s-t]  + vp[h, 1023+s-t]
// Computed as 128x128x64 split-bf16 mma tiles of the (t, j) rectangle with a
// shifted epilogue scatter s = j - 1023 + t. Tiles fully out of band exit.
// ---------------------------------------------------------------------------
#define PU_LDA 72
#define PU_AH 0
#define PU_AL 18432
#define PU_BH 36864
#define PU_BL 55296
#define PU_SMEM 73728

__global__ __launch_bounds__(256)
void posu_k(const float* __restrict__ q, const float* __restrict__ p,
            const float* __restrict__ vp, float* __restrict__ U)
{
    const int t0 = blockIdx.x << 7;
    const int n0 = blockIdx.y << 7;
    // band coverage: s = n - 1023 + t; tile alive iff some s in [0,1024)
    if (n0 + t0 + 254 < 1023 || n0 + t0 > 2046) return;

    extern __shared__ char smraw[];
    __nv_bfloat16* sm16 = (__nv_bfloat16*)smraw;
    const uint32_t smb = smem_u32(smraw);
    const int bh = blockIdx.z, h = bh & 7;
    const int tid = threadIdx.x, lane = tid & 31, wid = tid >> 5;
    const int warp_m = wid >> 2, warp_n = wid & 3;

    const float* qb = q + ((size_t)bh * NT + t0) * NDH;
    const float* pb = p + (size_t)h * NSPOS * NDH;

    // load fp32, split to hi/lo bf16 tiles (row stride 72 bf16)
#pragma unroll
    for (int pp = 0; pp < 8; pp++) {
        int e = tid + (pp << 8);
        int r = e >> 4, d = (e & 15) << 2;
        int ofs = r * PU_LDA + d;
        float4 va = *(const float4*)(qb + r * NDH + d);
        split4(va, sm16 + (PU_AH / 2) + ofs, sm16 + (PU_AL / 2) + ofs);
        int pr = n0 + r;
        float4 vb = (pr < NSPOS) ? *(const float4*)(pb + (size_t)pr * NDH + d)
                                 : make_float4(0.f, 0.f, 0.f, 0.f);
        split4(vb, sm16 + (PU_BH / 2) + ofs, sm16 + (PU_BL / 2) + ofs);
    }
    __syncthreads();

    float acc[4][4][4];
#pragma unroll
    for (int mi = 0; mi < 4; mi++)
#pragma unroll
        for (int ni = 0; ni < 4; ni++)
#pragma unroll
            for (int e = 0; e < 4; e++) acc[mi][ni][e] = 0.f;

    const int a_row = warp_m * 64 + (lane & 7) + ((lane >> 3) & 1) * 8;
    const int b_row = warp_n * 32 + (lane & 7) + ((lane >> 3) & 1) * 8;
    const int lm_k  = (lane >> 4) * 8;

#pragma unroll
    for (int ks = 0; ks < 4; ks++) {
        const int kofs = ks * 16 + lm_k;
        uint32_t bh2[2][4], bl2[2][4];
#pragma unroll
        for (int pq = 0; pq < 2; pq++) {
            uint32_t off = (uint32_t)((b_row + pq * 16) * PU_LDA + kofs) * 2;
            LDSM4(bh2[pq], smb + PU_BH + off);
            LDSM4(bl2[pq], smb + PU_BL + off);
        }
#pragma unroll
        for (int mi = 0; mi < 4; mi++) {
            uint32_t ah[4], al[4];
            uint32_t off = (uint32_t)((a_row + mi * 16) * PU_LDA + kofs) * 2;
            LDSM4(ah, smb + PU_AH + off);
            LDSM4(al, smb + PU_AL + off);
#pragma unroll
            for (int ni = 0; ni < 4; ni++) {
                const int pq = ni >> 1, hi = ni & 1;
                MMA16816(acc[mi][ni], ah, bh2[pq][hi], bh2[pq][hi + 2]);
                MMA16816(acc[mi][ni], ah, bl2[pq][hi], bl2[pq][hi + 2]);
                MMA16816(acc[mi][ni], al, bh2[pq][hi], bh2[pq][hi + 2]);
            }
        }
    }

    float* Ub = U + (size_t)bh * (1024 * 1024);
#pragma unroll
    for (int ni = 0; ni < 4; ni++) {
        const int n = n0 + warp_n * 32 + ni * 8 + (lane & 3) * 2;  // n <= 2046
        const float vp0 = vp[h * NSPOS + n];
        const float vp1 = (n + 1 < NSPOS) ? vp[h * NSPOS + n + 1] : 0.f;
#pragma unroll
        for (int mi = 0; mi < 4; mi++) {
            const int mr = t0 + warp_m * 64 + mi * 16 + (lane >> 2);
#pragma unroll
            for (int half = 0; half < 2; half++) {
                const int m = mr + half * 8;
                const int s0_ = n - 1023 + m;
                if (s0_ >= 0 && s0_ < 1024)
                    Ub[(size_t)m * 1024 + s0_] = acc[mi][ni][half * 2] + vp0;
                const int s1_ = s0_ + 1;
                if (s1_ >= 0 && s1_ < 1024)
                    Ub[(size_t)m * 1024 + s1_] = acc[mi][ni][half * 2 + 1] + vp1;
            }
        }
    }
}

// ---------------------------------------------------------------------------
// Flash attention (R11 shape, 256 thr, 8x4 frags) with pos band read from Uc.
// S[t,s] = q.k + uk[s] + Uc[t][s], then *SCALE.
// ---------------------------------------------------------------------------
#define SQ_OFF 0               // [128][64] swizzled
#define SK_OFF 8192            // [64][64] swizzled
#define SV_OFF 12288           // [64][68] linear
#define SPR_OFF 16640          // [128][66]
#define SUK_OFF 25088          // [64]
#define SM_FLOATS 25152

__global__ __launch_bounds__(256)
void attn_k(const float* __restrict__ q, const float* __restrict__ k,
            const float* __restrict__ v, const float* __restrict__ uk,
            const float* __restrict__ U, float* __restrict__ out)
{
    extern __shared__ float sm[];
    float* sq  = sm + SQ_OFF;
    float* sk_ = sm + SK_OFF;
    float* sv_ = sm + SV_OFF;
    float* sPs = sm + SPR_OFF;
    float* suk = sm + SUK_OFF;

    const int tid = threadIdx.x;
    const int tx = tid >> 4;     // 0..15 (row group, r = tx+16i)
    const int ty = tid & 15;     // 0..15 (col group, c = ty+16j)
    const int bx = blockIdx.x;
    const int t0 = (bx & 7) << 7;
    const int bh = bx >> 3;
    const int h  = bh & 7;
    const int b  = bh >> 3;

    const float* qb = q + ((size_t)bh * NT + t0) * NDH;
    const float* kb = k + (size_t)bh * NT * NDH;
    const float* vb = v + (size_t)bh * NT * NDH;
    const float* Ubase = U + (size_t)bh * (1024 * 1024) + (size_t)(t0 + tx) * 1024 + ty;

#pragma unroll
    for (int pp = 0; pp < 8; pp++) {
        int e = tid + (pp << 8);
        int r = e >> 4;
        int c4 = e & 15;
        float4 t = *(const float4*)(qb + r * NDH + (c4 << 2));
        *(float4*)(sq + r * 64 + (((c4 ^ (r & 15)) << 2))) = t;
    }

    ull O2[8][2];
    float m_i[8], l_i[8];
#pragma unroll
    for (int i = 0; i < 8; i++) {
        m_i[i] = -3.0e38f;
        l_i[i] = 0.f;
        O2[i][0] = 0ull;
        O2[i][1] = 0ull;
    }

    for (int s0 = 0; s0 < NT; s0 += 64) {
        __syncthreads();
        // prefetch the pos-score band (consumed after the score loop)
        float ubv[8][4];
        {
            const float* Ut = Ubase + s0;
#pragma unroll
            for (int i = 0; i < 8; i++)
#pragma unroll
                for (int j = 0; j < 4; j++)
                    ubv[i][j] = Ut[(size_t)(i << 4) * 1024 + (j << 4)];
        }
        // K (swizzled) and V (linear) tiles
#pragma unroll
        for (int pp = 0; pp < 4; pp++) {
            int e = tid + (pp << 8);
            int r = e >> 4;
            int c4 = e & 15;
            float4 kk = *(const float4*)(kb + (size_t)(s0 + r) * NDH + (c4 << 2));
            *(float4*)(sk_ + r * 64 + ((c4 ^ (r & 15)) << 2)) = kk;
            float4 vv = *(const float4*)(vb + (size_t)(s0 + r) * NDH + (c4 << 2));
            *(float4*)(sv_ + r * 68 + (c4 << 2)) = vv;
        }
        if (tid < 64) suk[tid] = uk[bh * NT + s0 + tid];
        __syncthreads();

        // ---- content scores: LDS.128 + f32x2 FMA ----
        ull S2[8][4];
#pragma unroll
        for (int i = 0; i < 8; i++)
#pragma unroll
            for (int j = 0; j < 4; j++) S2[i][j] = 0ull;

#pragma unroll 2
        for (int c4 = 0; c4 < 16; c4++) {
            ulonglong2 qv[8], kv[4];
            const int qoff = (c4 ^ tx) << 2;
            const int koff = (c4 ^ ty) << 2;
#pragma unroll
            for (int i = 0; i < 8; i++)
                qv[i] = *(const ulonglong2*)(sq + (tx + (i << 4)) * 64 + qoff);
#pragma unroll
            for (int j = 0; j < 4; j++)
                kv[j] = *(const ulonglong2*)(sk_ + (ty + (j << 4)) * 64 + koff);
#pragma unroll
            for (int i = 0; i < 8; i++)
#pragma unroll
                for (int j = 0; j < 4; j++) {
                    ffma2(S2[i][j], qv[i].x, kv[j].x);
                    ffma2(S2[i][j], qv[i].y, kv[j].y);
                }
        }

        // ---- online softmax ----
#pragma unroll
        for (int i = 0; i < 8; i++) {
            float s[4];
            float mt = -3.0e38f;
#pragma unroll
            for (int j = 0; j < 4; j++) {
                float2 f = unpk(S2[i][j]);
                s[j] = (f.x + f.y + suk[ty + (j << 4)] + ubv[i][j]) * ATT_SCALE;
                mt = fmaxf(mt, s[j]);
            }
#pragma unroll
            for (int off = 8; off >= 1; off >>= 1)
                mt = fmaxf(mt, __shfl_xor_sync(0xffffffffu, mt, off));
            float mn = fmaxf(m_i[i], mt);
            float alpha = __expf(m_i[i] - mn);
            m_i[i] = mn;
            float rs = 0.f;
#pragma unroll
            for (int j = 0; j < 4; j++) {
                float ev = __expf(s[j] - mn);
                s[j] = ev;
                rs += ev;
            }
#pragma unroll
            for (int off = 8; off >= 1; off >>= 1)
                rs += __shfl_xor_sync(0xffffffffu, rs, off);
            l_i[i] = l_i[i] * alpha + rs;
            ull ad = fdup(alpha);
            fmul2(O2[i][0], ad);
            fmul2(O2[i][1], ad);
#pragma unroll
            for (int j = 0; j < 4; j++)
                sPs[(tx + (i << 4)) * 66 + ty + (j << 4)] = s[j];
        }
        __syncthreads();

        // ---- O += P @ V ----
#pragma unroll 4
        for (int c = 0; c < 64; c++) {
            ulonglong2 vv = *(const ulonglong2*)(sv_ + c * 68 + (ty << 2));
#pragma unroll
            for (int i = 0; i < 8; i++) {
                ull pd = fdup(sPs[(tx + (i << 4)) * 66 + c]);
                ffma2(O2[i][0], pd, vv.x);
                ffma2(O2[i][1], pd, vv.y);
            }
        }
    }

    // normalize, write to [b][t][h*64+d]
#pragma unroll
    for (int i = 0; i < 8; i++) {
        float inv = 1.f / l_i[i];
        float2 a = unpk(O2[i][0]);
        float2 c2 = unpk(O2[i][1]);
        float4 o;
        o.x = a.x * inv;  o.y = a.y * inv;
        o.z = c2.x * inv; o.w = c2.y * inv;
        int r = tx + (i << 4);
        *(float4*)(out + ((size_t)b * NT + t0 + r) * ND + h * NDH + (ty << 2)) = o;
    }
}

// ---------------------------------------------------------------------------
extern "C" void kernel_launch(void* const* d_in, const int* in_sizes, int n_in,
                              void* d_out, int out_size)
{
    const float* x    = (const float*)d_in[0];
    const float* pe   = (const float*)d_in[1];
    const float* Wq   = (const float*)d_in[2];
    const float* bq   = (const float*)d_in[3];
    const float* Wk   = (const float*)d_in[4];
    const float* bk   = (const float*)d_in[5];
    const float* Wv   = (const float*)d_in[6];
    const float* bv   = (const float*)d_in[7];
    const float* Wpos = (const float*)d_in[8];
    const float* pbu  = (const float*)d_in[9];
    const float* pbv  = (const float*)d_in[10];
    const float* Wo   = (const float*)d_in[11];
    const float* bo   = (const float*)d_in[12];
    float* out = (float*)d_out;

    float *qp, *kp, *vp_, *pp, *aop, *ukp, *vpp, *pup;
    cudaGetSymbolAddress((void**)&qp,  g_q);
    cudaGetSymbolAddress((void**)&kp,  g_k);
    cudaGetSymbolAddress((void**)&vp_, g_v);
    cudaGetSymbolAddress((void**)&pp,  g_p);
    cudaGetSymbolAddress((void**)&aop, g_ao);
    cudaGetSymbolAddress((void**)&ukp, g_uk);
    cudaGetSymbolAddress((void**)&vpp, g_vp);
    cudaGetSymbolAddress((void**)&pup, g_posu);
    __nv_bfloat16 *xh, *xl, *peh, *pel, *wth, *wtl, *aoh, *aol;
    cudaGetSymbolAddress((void**)&xh,  g_xh);
    cudaGetSymbolAddress((void**)&xl,  g_xl);
    cudaGetSymbolAddress((void**)&peh, g_peh);
    cudaGetSymbolAddress((void**)&pel, g_pel);
    cudaGetSymbolAddress((void**)&wth, g_wth);
    cudaGetSymbolAddress((void**)&wtl, g_wtl);
    cudaGetSymbolAddress((void**)&aoh, g_aoh);
    cudaGetSymbolAddress((void**)&aol, g_aol);

    cudaFuncSetAttribute(mmagemm_fused_k, cudaFuncAttributeMaxDynamicSharedMemorySize, MT_SMEM);
    cudaFuncSetAttribute(mmagemm_k<0>,    cudaFuncAttributeMaxDynamicSharedMemorySize, MT_SMEM);
    cudaFuncSetAttribute(posu_k,          cudaFuncAttributeMaxDynamicSharedMemorySize, PU_SMEM);
    const int smem = SM_FLOATS * (int)sizeof(float);   // 100608 B
    cudaFuncSetAttribute(attn_k, cudaFuncAttributeMaxDynamicSharedMemorySize, smem);

    const size_t WSZ = (size_t)ND * ND;
    dim3 blk(256);

    split_k<<<(NB*NT*ND/4 + 255)/256, blk>>>(x,  xh,  xl,  NB*NT*ND/4);
    split_k<<<(NSPOS*ND/4 + 255)/256, blk>>>(pe, peh, pel, NSPOS*ND/4);
    wsplit_k<<<dim3(16, 16, 5), blk>>>(Wq, Wk, Wv, Wpos, Wo, wth, wtl);

    mmagemm_fused_k<<<dim3(64, 4, 4), blk, MT_SMEM>>>(xh, xl, peh, pel, wth, wtl,
                                                      bq, bk, bv, qp, kp, vp_, pp);
    biasdot_k<<<(NUKROWS + NVPROWS + 7) / 8, blk>>>(kp, pp, pbu, pbv, ukp, vpp);
    posu_k<<<dim3(8, 16, 64), blk, PU_SMEM>>>(qp, pp, vpp, pup);
    attn_k<<<NB * NH * (NT / 128), blk, smem>>>(qp, kp, vp_, ukp, pup, aop);
    split_k<<<(NB*NT*ND/4 + 255)/256, blk>>>(aop, aoh, aol, NB*NT*ND/4);
    mmagemm_k<0><<<dim3(64, 4), blk, MT_SMEM>>>(aoh, aol, wth + 4*WSZ, wtl + 4*WSZ,
                                                bo, out, NB * NT);
}

// round 14
// speedup vs baseline: 1.6832x; 1.6832x over previous
#include <cuda_runtime.h>
#include <cuda_bf16.h>
#include <cstdint>

#define NB 8
#define NT 1024
#define ND 512
#define NH 8
#define NDH 64
#define NSPOS 2047
#define ATT_SCALE 0.125f

typedef unsigned long long ull;

// ---------------- scratch (device globals; no allocs allowed) ----------------
__device__ float g_q[NB*NH*NT*NDH];
__device__ float g_k[NB*NH*NT*NDH];
__device__ float g_v[NB*NH*NT*NDH];
__device__ float g_p[NH*NSPOS*NDH];
__device__ __nv_bfloat16 g_xh[NB*NT*ND],  g_xl[NB*NT*ND];
__device__ __nv_bfloat16 g_peh[2048*ND],  g_pel[2048*ND];
__device__ __nv_bfloat16 g_wth[5*ND*ND],  g_wtl[5*ND*ND];
__device__ __nv_bfloat16 g_aoh[NB*NT*ND], g_aol[NB*NT*ND];

// ---------------- scalar f32x2 helpers ----------------
__device__ __forceinline__ void ffma2(ull &d, ull a, ull b) {
    asm("fma.rn.f32x2 %0, %1, %2, %0;" : "+l"(d) : "l"(a), "l"(b));
}
__device__ __forceinline__ void fmul2(ull &d, ull a) {
    asm("mul.rn.f32x2 %0, %0, %1;" : "+l"(d) : "l"(a));
}
__device__ __forceinline__ ull fdup(float x) {
    ull r; asm("mov.b64 %0, {%1, %1};" : "=l"(r) : "f"(x)); return r;
}
__device__ __forceinline__ float2 unpk(ull v) {
    float2 f; asm("mov.b64 {%0, %1}, %2;" : "=f"(f.x), "=f"(f.y) : "l"(v)); return f;
}

// ---------------- mma.sync / ldmatrix / cp.async helpers ----------------
__device__ __forceinline__ uint32_t smem_u32(const void* p) {
    uint32_t a;
    asm("{ .reg .u64 t; cvta.to.shared.u64 t, %1; cvt.u32.u64 %0, t; }" : "=r"(a) : "l"(p));
    return a;
}
#define LDSM4(r, addr) \
    asm volatile("ldmatrix.sync.aligned.m8n8.x4.shared.b16 {%0,%1,%2,%3}, [%4];" \
        : "=r"((r)[0]), "=r"((r)[1]), "=r"((r)[2]), "=r"((r)[3]) : "r"(addr))
#define MMA16816(c, a, b0, b1) \
    asm volatile("mma.sync.aligned.m16n8k16.row.col.f32.bf16.bf16.f32 " \
        "{%0,%1,%2,%3}, {%4,%5,%6,%7}, {%8,%9}, {%0,%1,%2,%3};" \
        : "+f"((c)[0]), "+f"((c)[1]), "+f"((c)[2]), "+f"((c)[3]) \
        : "r"((a)[0]), "r"((a)[1]), "r"((a)[2]), "r"((a)[3]), "r"(b0), "r"(b1))
__device__ __forceinline__ void cpa16(uint32_t dst, const void* src, int sz) {
    asm volatile("cp.async.cg.shared.global [%0], [%1], 16, %2;"
                 :: "r"(dst), "l"(src), "r"(sz) : "memory");
}
__device__ __forceinline__ void cpa_commit() {
    asm volatile("cp.async.commit_group;" ::: "memory");
}
__device__ __forceinline__ void cpa_wait0() {
    asm volatile("cp.async.wait_group 0;" ::: "memory");
}

// split a float4 into hi/lo bf16 quads
__device__ __forceinline__ void split4(float4 v, __nv_bfloat16* hdst, __nv_bfloat16* ldst) {
    __nv_bfloat16 h0 = __float2bfloat16(v.x), h1 = __float2bfloat16(v.y);
    __nv_bfloat16 h2 = __float2bfloat16(v.z), h3 = __float2bfloat16(v.w);
    ((__nv_bfloat162*)hdst)[0] = __nv_bfloat162(h0, h1);
    ((__nv_bfloat162*)hdst)[1] = __nv_bfloat162(h2, h3);
    ((__nv_bfloat162*)ldst)[0] = __nv_bfloat162(
        __float2bfloat16(v.x - __bfloat162float(h0)),
        __float2bfloat16(v.y - __bfloat162float(h1)));
    ((__nv_bfloat162*)ldst)[1] = __nv_bfloat162(
        __float2bfloat16(v.z - __bfloat162float(h2)),
        __float2bfloat16(v.w - __bfloat162float(h3)));
}

// ---------------- split-precision convert kernels ----------------
__global__ __launch_bounds__(256)
void split_k(const float* __restrict__ s, __nv_bfloat16* __restrict__ h,
             __nv_bfloat16* __restrict__ l, int n4)
{
    int i = blockIdx.x * 256 + threadIdx.x;
    if (i >= n4) return;
    float4 v = ((const float4*)s)[i];
    split4(v, h + i * 4, l + i * 4);
}

// Transpose + split the 5 weight matrices: wt[z][n][k] = W_z[k][n]
__global__ __launch_bounds__(256)
void wsplit_k(const float* __restrict__ W0, const float* __restrict__ W1,
              const float* __restrict__ W2, const float* __restrict__ W3,
              const float* __restrict__ W4,
              __nv_bfloat16* __restrict__ th, __nv_bfloat16* __restrict__ tl)
{
    const float* W;
    switch (blockIdx.z) {
        case 0: W = W0; break;
        case 1: W = W1; break;
        case 2: W = W2; break;
        case 3: W = W3; break;
        default: W = W4; break;
    }
    __shared__ float t[32][33];
    int tx = threadIdx.x & 31, ty = threadIdx.x >> 5;
    int n0 = blockIdx.x * 32, k0 = blockIdx.y * 32;
#pragma unroll
    for (int ph = 0; ph < 4; ph++)
        t[ty + ph * 8][tx] = W[(size_t)(k0 + ty + ph * 8) * ND + n0 + tx];
    __syncthreads();
    size_t base = (size_t)blockIdx.z * ND * ND;
#pragma unroll
    for (int ph = 0; ph < 4; ph++) {
        int n = n0 + ty + ph * 8, k = k0 + tx;
        float v = t[tx][ty + ph * 8];
        __nv_bfloat16 hh = __float2bfloat16(v);
        __nv_bfloat16 ll = __float2bfloat16(v - __bfloat162float(hh));
        th[base + (size_t)n * ND + k] = hh;
        tl[base + (size_t)n * ND + k] = ll;
    }
}

// ---------------------------------------------------------------------------
// mma.sync split-bf16 GEMM (proven in R11).
// ---------------------------------------------------------------------------
#define MT_AH 0
#define MT_AL 10240
#define MT_BH 20480
#define MT_BL 30720
#define MT_BUF 40960
#define MT_SMEM 81920

template<int MODE>
__device__ __forceinline__
void mmagemm_body(const __nv_bfloat16* __restrict__ Ah, const __nv_bfloat16* __restrict__ Al,
                  const __nv_bfloat16* __restrict__ Bh, const __nv_bfloat16* __restrict__ Bl,
                  const float* __restrict__ bias, float* __restrict__ C,
                  int M, int row0, int col0, char* smraw)
{
    const int tid  = threadIdx.x;
    const int lane = tid & 31;
    const int wid  = tid >> 5;
    const int warp_m = wid >> 2;
    const int warp_n = wid & 3;
    const uint32_t smb = smem_u32(smraw);

    const int ldrow = tid >> 1;
    const int ldc8  = (tid & 1) * 16;
    const bool okA  = (row0 + ldrow) < M;
    const size_t agoff = (size_t)(row0 + ldrow) * ND;
    const size_t bgoff = (size_t)(col0 + ldrow) * ND;
    const uint32_t srow = (uint32_t)ldrow * 40;
    const int szA = okA ? 16 : 0;

    float acc[4][4][4];
#pragma unroll
    for (int mi = 0; mi < 4; mi++)
#pragma unroll
        for (int ni = 0; ni < 4; ni++)
#pragma unroll
            for (int e = 0; e < 4; e++) acc[mi][ni][e] = 0.f;

    const int a_row = warp_m * 64 + (lane & 7) + ((lane >> 3) & 1) * 8;
    const int b_row = warp_n * 32 + (lane & 7) + ((lane >> 3) & 1) * 8;
    const int lm_k  = (lane >> 4) * 8;

    auto load_tile = [&](int k0, int buf) {
        uint32_t sb = smb + buf * MT_BUF;
#pragma unroll
        for (int c = 0; c < 2; c++) {
            int col = ldc8 + c * 8;
            uint32_t so = (srow + col) * 2;
            cpa16(sb + MT_AH + so, Ah + agoff + k0 + col, szA);
            cpa16(sb + MT_AL + so, Al + agoff + k0 + col, szA);
            cpa16(sb + MT_BH + so, Bh + bgoff + k0 + col, 16);
            cpa16(sb + MT_BL + so, Bl + bgoff + k0 + col, 16);
        }
    };

    load_tile(0, 0);
    cpa_commit();

    int buf = 0;
    for (int it = 0; it < 16; it++) {
        cpa_wait0();
        __syncthreads();
        if (it < 15) {
            load_tile((it + 1) * 32, buf ^ 1);
            cpa_commit();
        }
        const uint32_t sb = smb + buf * MT_BUF;
#pragma unroll
        for (int ks = 0; ks < 2; ks++) {
            const int kofs = ks * 16 + lm_k;
            uint32_t bh[2][4], bl[2][4];
#pragma unroll
            for (int p = 0; p < 2; p++) {
                uint32_t off = (uint32_t)((b_row + p * 16) * 40 + kofs) * 2;
                LDSM4(bh[p], sb + MT_BH + off);
                LDSM4(bl[p], sb + MT_BL + off);
            }
#pragma unroll
            for (int mi = 0; mi < 4; mi++) {
                uint32_t ah[4], al[4];
                uint32_t off = (uint32_t)((a_row + mi * 16) * 40 + kofs) * 2;
                LDSM4(ah, sb + MT_AH + off);
                LDSM4(al, sb + MT_AL + off);
#pragma unroll
                for (int ni = 0; ni < 4; ni++) {
                    const int p = ni >> 1, hi = ni & 1;
                    MMA16816(acc[mi][ni], ah, bh[p][hi], bh[p][hi + 2]);
                    MMA16816(acc[mi][ni], ah, bl[p][hi], bl[p][hi + 2]);
                    MMA16816(acc[mi][ni], al, bh[p][hi], bh[p][hi + 2]);
                }
            }
        }
        buf ^= 1;
    }

#pragma unroll
    for (int mi = 0; mi < 4; mi++) {
        const int r0 = row0 + warp_m * 64 + mi * 16 + (lane >> 2);
#pragma unroll
        for (int ni = 0; ni < 4; ni++) {
            const int col = col0 + warp_n * 32 + ni * 8 + (lane & 3) * 2;
            const float b0 = bias ? bias[col] : 0.f;
            const float b1 = bias ? bias[col + 1] : 0.f;
#pragma unroll
            for (int half = 0; half < 2; half++) {
                const int m = r0 + half * 8;
                if (m >= M) continue;
                float2 o;
                o.x = acc[mi][ni][half * 2 + 0] + b0;
                o.y = acc[mi][ni][half * 2 + 1] + b1;
                if (MODE == 0) {
                    *(float2*)(C + (size_t)m * ND + col) = o;
                } else if (MODE == 1) {
                    int b = m >> 10, t = m & 1023;
                    int h = col >> 6, d = col & 63;
                    *(float2*)(C + ((size_t)((b << 3) + h) * NT + t) * NDH + d) = o;
                } else {
                    int h = col >> 6, d = col & 63;
                    *(float2*)(C + ((size_t)h * NSPOS + m) * NDH + d) = o;
                }
            }
        }
    }
}

template<int MODE>
__global__ __launch_bounds__(256, 2)
void mmagemm_k(const __nv_bfloat16* __restrict__ Ah, const __nv_bfloat16* __restrict__ Al,
               const __nv_bfloat16* __restrict__ Bh, const __nv_bfloat16* __restrict__ Bl,
               const float* __restrict__ bias, float* __restrict__ C, int M)
{
    extern __shared__ char smraw[];
    mmagemm_body<MODE>(Ah, Al, Bh, Bl, bias, C, M,
                       blockIdx.x << 7, blockIdx.y << 7, smraw);
}

__global__ __launch_bounds__(256, 2)
void mmagemm_fused_k(const __nv_bfloat16* __restrict__ xh, const __nv_bfloat16* __restrict__ xl,
                     const __nv_bfloat16* __restrict__ peh, const __nv_bfloat16* __restrict__ pel,
                     const __nv_bfloat16* __restrict__ wth, const __nv_bfloat16* __restrict__ wtl,
                     const float* __restrict__ bq, const float* __restrict__ bk,
                     const float* __restrict__ bv,
                     float* __restrict__ Cq, float* __restrict__ Ck,
                     float* __restrict__ Cv, float* __restrict__ Cp)
{
    extern __shared__ char smraw[];
    const int z = blockIdx.z;
    const size_t WSZ = (size_t)ND * ND;
    if (z == 3) {
        if (blockIdx.x >= 16) return;
        mmagemm_body<2>(peh, pel, wth + 3 * WSZ, wtl + 3 * WSZ, nullptr, Cp, NSPOS,
                        blockIdx.x << 7, blockIdx.y << 7, smraw);
    } else {
        const float* bias = (z == 0) ? bq : (z == 1) ? bk : bv;
        float* C = (z == 0) ? Cq : (z == 1) ? Ck : Cv;
        mmagemm_body<1>(xh, xl, wth + z * WSZ, wtl + z * WSZ, bias, C, NB * NT,
                        blockIdx.x << 7, blockIdx.y << 7, smraw);
    }
}

// ---------------------------------------------------------------------------
// attn_k v3: 64q x 64k tiles, 1024 CTAs, 256 thr. Content score AND pos score
// on tensor pipe (split-bf16 mma.sync); pos scores via 128-column smem ring
// (window slides 64/iter; one 64x64x64 GEMM appends 64 ring columns).
// Qu = q+pbu (content A), Qv = q+pbv (pos A). Softmax + AV scalar.
// Ring col of global p-row j is (j - (960 - t0)) & 127; read index for
// S_pos[t0+r, s0+c] is (s0 + 63 + c - r) & 127.
// ---------------------------------------------------------------------------
#define AT_QUH 0
#define AT_QUL 9216
#define AT_QVH 18432
#define AT_QVL 27648
#define AT_KH  36864
#define AT_KL  46080
#define AT_PH  55296
#define AT_PL  64512
#define AT_RING 73728   // f32 [64][132]
#define AT_SS  107520   // f32 [64][66]
#define AT_SV  124416   // f32 [64][68]
#define AT_SPS 141824   // f32 [64][66]
#define AT_SMEM 158720

__global__ __launch_bounds__(256)
void attn_k(const float* __restrict__ q, const float* __restrict__ k,
            const float* __restrict__ v, const float* __restrict__ p,
            const float* __restrict__ pbu, const float* __restrict__ pbv,
            __nv_bfloat16* __restrict__ aoh, __nv_bfloat16* __restrict__ aol)
{
    extern __shared__ char smraw[];
    const uint32_t smb = smem_u32(smraw);
    __nv_bfloat16* sm16 = (__nv_bfloat16*)smraw;
    float* ring = (float*)(smraw + AT_RING);
    float* sS   = (float*)(smraw + AT_SS);
    float* sv_  = (float*)(smraw + AT_SV);
    float* sPs  = (float*)(smraw + AT_SPS);

    const int tid = threadIdx.x;
    const int lane = tid & 31, wid = tid >> 5;
    const int warp_m = wid & 3, warp_n = wid >> 2;
    const int tx = tid >> 4, ty = tid & 15;
    const int bx = blockIdx.x;
    const int t0 = (bx & 15) << 6;
    const int bh = bx >> 4;
    const int h = bh & 7, b = bh >> 3;

    const float* qb = q + ((size_t)bh * NT + t0) * NDH;
    const float* kb = k + (size_t)bh * NT * NDH;
    const float* vb = v + (size_t)bh * NT * NDH;
    const float* pb = p + (size_t)h * NSPOS * NDH;
    const int pj0 = 960 - t0;   // global p-row of ring block 0, col 0 (>= 0)

    const int a_row = warp_m * 16 + (lane & 7) + 8 * ((lane >> 3) & 1);
    const int b_row = warp_n * 32 + (lane & 7) + 8 * ((lane >> 3) & 1);
    const int lm_k  = (lane >> 4) * 8;
    const int fs_row = warp_m * 16 + (lane >> 2);
    const int fs_col = warp_n * 32 + (lane & 3) * 2;

    const int ldr = tid >> 2;           // 0..63
    const int ldd = (tid & 3) << 4;     // 0,16,32,48

    // ---- stage Qu/Qv (once) ----
#pragma unroll
    for (int c = 0; c < 4; c++) {
        int d = ldd + c * 4;
        float4 qq = *(const float4*)(qb + ldr * NDH + d);
        float4 uu = *(const float4*)(pbu + h * NDH + d);
        float4 vv = *(const float4*)(pbv + h * NDH + d);
        float4 qu = make_float4(qq.x+uu.x, qq.y+uu.y, qq.z+uu.z, qq.w+uu.w);
        float4 qv = make_float4(qq.x+vv.x, qq.y+vv.y, qq.z+vv.z, qq.w+vv.w);
        int ofs = ldr * 72 + d;
        split4(qu, sm16 + AT_QUH/2 + ofs, sm16 + AT_QUL/2 + ofs);
        split4(qv, sm16 + AT_QVH/2 + ofs, sm16 + AT_QVL/2 + ofs);
    }

    auto stage_p = [&](int blk) {
        int j = pj0 + blk * 64 + ldr;
        j = j > 2046 ? 2046 : j;
#pragma unroll
        for (int c = 0; c < 4; c++) {
            int d = ldd + c * 4;
            float4 pv = *(const float4*)(pb + (size_t)j * NDH + d);
            int ofs = ldr * 72 + d;
            split4(pv, sm16 + AT_PH/2 + ofs, sm16 + AT_PL/2 + ofs);
        }
    };
    auto stage_kv = [&](int n) {
        const float* krow = kb + (size_t)(n * 64 + ldr) * NDH;
        const float* vrow = vb + (size_t)(n * 64 + ldr) * NDH;
#pragma unroll
        for (int c = 0; c < 4; c++) {
            int d = ldd + c * 4;
            float4 kk = *(const float4*)(krow + d);
            int ofs = ldr * 72 + d;
            split4(kk, sm16 + AT_KH/2 + ofs, sm16 + AT_KL/2 + ofs);
            *(float4*)(sv_ + ldr * 68 + d) = *(const float4*)(vrow + d);
        }
    };

    // generic 64x64x64 split MMA from (Ah,Al)=(aoffH,aoffL), (Bh,Bl) smem tiles
    auto mma_tile = [&](uint32_t aH, uint32_t aL, uint32_t bH, uint32_t bL,
                        float cc[4][4]) {
#pragma unroll
        for (int ni = 0; ni < 4; ni++)
#pragma unroll
            for (int e = 0; e < 4; e++) cc[ni][e] = 0.f;
#pragma unroll
        for (int ks = 0; ks < 4; ks++) {
            const int kofs = ks * 16 + lm_k;
            uint32_t ah[4], al[4], bh2[2][4], bl2[2][4];
            LDSM4(ah, aH + (uint32_t)(a_row * 72 + kofs) * 2);
            LDSM4(al, aL + (uint32_t)(a_row * 72 + kofs) * 2);
#pragma unroll
            for (int p2 = 0; p2 < 2; p2++) {
                uint32_t off = (uint32_t)((b_row + p2 * 16) * 72 + kofs) * 2;
                LDSM4(bh2[p2], bH + off);
                LDSM4(bl2[p2], bL + off);
            }
#pragma unroll
            for (int ni = 0; ni < 4; ni++) {
                const int p2 = ni >> 1, hi = ni & 1;
                MMA16816(cc[ni], ah, bh2[p2][hi], bh2[p2][hi + 2]);
                MMA16816(cc[ni], ah, bl2[p2][hi], bl2[p2][hi + 2]);
                MMA16816(cc[ni], al, bh2[p2][hi], bh2[p2][hi + 2]);
            }
        }
    };

    auto pos_mma = [&](int blk) {
        float cc[4][4];
        mma_tile(smb + AT_QVH, smb + AT_QVL, smb + AT_PH, smb + AT_PL, cc);
        const int slot = (blk & 1) << 6;
#pragma unroll
        for (int ni = 0; ni < 4; ni++) {
            int col = slot + fs_col + ni * 8;
            *(float2*)(ring + fs_row * 132 + col)       = make_float2(cc[ni][0], cc[ni][1]);
            *(float2*)(ring + (fs_row + 8) * 132 + col) = make_float2(cc[ni][2], cc[ni][3]);
        }
    };

    // ---- preamble: ring blocks 0,1 and k0/v0 ----
    stage_p(0);
    __syncthreads();
    pos_mma(0);
    __syncthreads();
    stage_p(1);
    stage_kv(0);
    __syncthreads();
    pos_mma(1);

    ull O2[4][2];
    float m_i[4], l_i[4];
#pragma unroll
    for (int i = 0; i < 4; i++) {
        m_i[i] = -3.0e38f;
        l_i[i] = 0.f;
        O2[i][0] = 0ull;
        O2[i][1] = 0ull;
    }

    for (int n = 0; n < 16; n++) {
        // ---- content score MMA -> sS ----
        {
            float cc[4][4];
            mma_tile(smb + AT_QUH, smb + AT_QUL, smb + AT_KH, smb + AT_KL, cc);
#pragma unroll
            for (int ni = 0; ni < 4; ni++) {
                int col = fs_col + ni * 8;
                *(float2*)(sS + fs_row * 66 + col)       = make_float2(cc[ni][0], cc[ni][1]);
                *(float2*)(sS + (fs_row + 8) * 66 + col) = make_float2(cc[ni][2], cc[ni][3]);
            }
        }
        __syncthreads();

        // ---- softmax (rows r = tx+16i, cols c = ty+16j) ----
        const int pw = (n << 6) + 63;
#pragma unroll
        for (int i = 0; i < 4; i++) {
            const int r = tx + (i << 4);
            float s[4];
            float mt = -3.0e38f;
#pragma unroll
            for (int j = 0; j < 4; j++) {
                const int c = ty + (j << 4);
                const int rc = (pw + c - r) & 127;
                s[j] = (sS[r * 66 + c] + ring[r * 132 + rc]) * ATT_SCALE;
                mt = fmaxf(mt, s[j]);
            }
#pragma unroll
            for (int off = 8; off >= 1; off >>= 1)
                mt = fmaxf(mt, __shfl_xor_sync(0xffffffffu, mt, off));
            float mn = fmaxf(m_i[i], mt);
            float alpha = __expf(m_i[i] - mn);
            m_i[i] = mn;
            float rs = 0.f;
#pragma unroll
            for (int j = 0; j < 4; j++) {
                float ev = __expf(s[j] - mn);
                s[j] = ev;
                rs += ev;
            }
#pragma unroll
            for (int off = 8; off >= 1; off >>= 1)
                rs += __shfl_xor_sync(0xffffffffu, rs, off);
            l_i[i] = l_i[i] * alpha + rs;
            ull ad = fdup(alpha);
            fmul2(O2[i][0], ad);
            fmul2(O2[i][1], ad);
#pragma unroll
            for (int j = 0; j < 4; j++)
                sPs[r * 66 + ty + (j << 4)] = s[j];
        }
        __syncwarp();

        // ---- AV scalar ----
#pragma unroll 4
        for (int c = 0; c < 64; c++) {
            ulonglong2 vv = *(const ulonglong2*)(sv_ + c * 68 + (ty << 2));
#pragma unroll
            for (int i = 0; i < 4; i++) {
                ull pd = fdup(sPs[(tx + (i << 4)) * 66 + c]);
                ffma2(O2[i][0], pd, vv.x);
                ffma2(O2[i][1], pd, vv.y);
            }
        }
        __syncthreads();

        // ---- stage next K/V and p-block; pos MMA appends ring ----
        if (n < 15) stage_kv(n + 1);
        const bool havep = (n + 2) <= 16;
        if (havep) stage_p(n + 2);
        __syncthreads();
        if (havep) pos_mma(n + 2);
        // next iteration's post-content __syncthreads makes ring visible
    }

    // ---- epilogue: normalize, write split-bf16 ao ----
#pragma unroll
    for (int i = 0; i < 4; i++) {
        float inv = 1.f / l_i[i];
        float2 a = unpk(O2[i][0]);
        float2 c2 = unpk(O2[i][1]);
        float4 o = make_float4(a.x * inv, a.y * inv, c2.x * inv, c2.y * inv);
        int r = tx + (i << 4);
        size_t idx = ((size_t)b * NT + t0 + r) * ND + h * NDH + (ty << 2);
        split4(o, aoh + idx, aol + idx);
    }
}

// ---------------------------------------------------------------------------
extern "C" void kernel_launch(void* const* d_in, const int* in_sizes, int n_in,
                              void* d_out, int out_size)
{
    const float* x    = (const float*)d_in[0];
    const float* pe   = (const float*)d_in[1];
    const float* Wq   = (const float*)d_in[2];
    const float* bq   = (const float*)d_in[3];
    const float* Wk   = (const float*)d_in[4];
    const float* bk   = (const float*)d_in[5];
    const float* Wv   = (const float*)d_in[6];
    const float* bv   = (const float*)d_in[7];
    const float* Wpos = (const float*)d_in[8];
    const float* pbu  = (const float*)d_in[9];
    const float* pbv  = (const float*)d_in[10];
    const float* Wo   = (const float*)d_in[11];
    const float* bo   = (const float*)d_in[12];
    float* out = (float*)d_out;

    float *qp, *kp, *vp_, *pp;
    cudaGetSymbolAddress((void**)&qp,  g_q);
    cudaGetSymbolAddress((void**)&kp,  g_k);
    cudaGetSymbolAddress((void**)&vp_, g_v);
    cudaGetSymbolAddress((void**)&pp,  g_p);
    __nv_bfloat16 *xh, *xl, *peh, *pel, *wth, *wtl, *aoh, *aol;
    cudaGetSymbolAddress((void**)&xh,  g_xh);
    cudaGetSymbolAddress((void**)&xl,  g_xl);
    cudaGetSymbolAddress((void**)&peh, g_peh);
    cudaGetSymbolAddress((void**)&pel, g_pel);
    cudaGetSymbolAddress((void**)&wth, g_wth);
    cudaGetSymbolAddress((void**)&wtl, g_wtl);
    cudaGetSymbolAddress((void**)&aoh, g_aoh);
    cudaGetSymbolAddress((void**)&aol, g_aol);

    cudaFuncSetAttribute(mmagemm_fused_k, cudaFuncAttributeMaxDynamicSharedMemorySize, MT_SMEM);
    cudaFuncSetAttribute(mmagemm_k<0>,    cudaFuncAttributeMaxDynamicSharedMemorySize, MT_SMEM);
    cudaFuncSetAttribute(attn_k,          cudaFuncAttributeMaxDynamicSharedMemorySize, AT_SMEM);

    const size_t WSZ = (size_t)ND * ND;
    dim3 blk(256);

    split_k<<<(NB*NT*ND/4 + 255)/256, blk>>>(x,  xh,  xl,  NB*NT*ND/4);
    split_k<<<(NSPOS*ND/4 + 255)/256, blk>>>(pe, peh, pel, NSPOS*ND/4);
    wsplit_k<<<dim3(16, 16, 5), blk>>>(Wq, Wk, Wv, Wpos, Wo, wth, wtl);

    mmagemm_fused_k<<<dim3(64, 4, 4), blk, MT_SMEM>>>(xh, xl, peh, pel, wth, wtl,
                                                      bq, bk, bv, qp, kp, vp_, pp);
    attn_k<<<NB * NH * (NT / 64), blk, AT_SMEM>>>(qp, kp, vp_, pp, pbu, pbv, aoh, aol);
    mmagemm_k<0><<<dim3(64, 4), blk, MT_SMEM>>>(aoh, aol, wth + 4*WSZ, wtl + 4*WSZ,
                                                bo, out, NB * NT);
}

// round 16
// speedup vs baseline: 1.9137x; 1.1369x over previous
#include <cuda_runtime.h>
#include <cuda_bf16.h>
#include <cstdint>

#define NB 8
#define NT 1024
#define ND 512
#define NH 8
#define NDH 64
#define NSPOS 2047
#define ATT_SCALE 0.125f

typedef unsigned long long ull;

// ---------------- scratch (device globals; no allocs allowed) ----------------
__device__ float g_q[NB*NH*NT*NDH];
__device__ float g_k[NB*NH*NT*NDH];
__device__ float g_v[NB*NH*NT*NDH];
__device__ float g_p[NH*NSPOS*NDH];
__device__ __nv_bfloat16 g_xh[NB*NT*ND],  g_xl[NB*NT*ND];
__device__ __nv_bfloat16 g_peh[2048*ND],  g_pel[2048*ND];
__device__ __nv_bfloat16 g_wth[5*ND*ND],  g_wtl[5*ND*ND];
__device__ __nv_bfloat16 g_aoh[NB*NT*ND], g_aol[NB*NT*ND];

// ---------------- mma.sync / ldmatrix / cp.async helpers ----------------
__device__ __forceinline__ uint32_t smem_u32(const void* p) {
    uint32_t a;
    asm("{ .reg .u64 t; cvta.to.shared.u64 t, %1; cvt.u32.u64 %0, t; }" : "=r"(a) : "l"(p));
    return a;
}
#define LDSM4(r, addr) \
    asm volatile("ldmatrix.sync.aligned.m8n8.x4.shared.b16 {%0,%1,%2,%3}, [%4];" \
        : "=r"((r)[0]), "=r"((r)[1]), "=r"((r)[2]), "=r"((r)[3]) : "r"(addr))
#define MMA16816(c, a, b0, b1) \
    asm volatile("mma.sync.aligned.m16n8k16.row.col.f32.bf16.bf16.f32 " \
        "{%0,%1,%2,%3}, {%4,%5,%6,%7}, {%8,%9}, {%0,%1,%2,%3};" \
        : "+f"((c)[0]), "+f"((c)[1]), "+f"((c)[2]), "+f"((c)[3]) \
        : "r"((a)[0]), "r"((a)[1]), "r"((a)[2]), "r"((a)[3]), "r"(b0), "r"(b1))
__device__ __forceinline__ void cpa16(uint32_t dst, const void* src, int sz) {
    asm volatile("cp.async.cg.shared.global [%0], [%1], 16, %2;"
                 :: "r"(dst), "l"(src), "r"(sz) : "memory");
}
__device__ __forceinline__ void cpa_commit() {
    asm volatile("cp.async.commit_group;" ::: "memory");
}
__device__ __forceinline__ void cpa_wait0() {
    asm volatile("cp.async.wait_group 0;" ::: "memory");
}

// split a float4 into hi/lo bf16 quads
__device__ __forceinline__ void split4(float4 v, __nv_bfloat16* hdst, __nv_bfloat16* ldst) {
    __nv_bfloat16 h0 = __float2bfloat16(v.x), h1 = __float2bfloat16(v.y);
    __nv_bfloat16 h2 = __float2bfloat16(v.z), h3 = __float2bfloat16(v.w);
    ((__nv_bfloat162*)hdst)[0] = __nv_bfloat162(h0, h1);
    ((__nv_bfloat162*)hdst)[1] = __nv_bfloat162(h2, h3);
    ((__nv_bfloat162*)ldst)[0] = __nv_bfloat162(
        __float2bfloat16(v.x - __bfloat162float(h0)),
        __float2bfloat16(v.y - __bfloat162float(h1)));
    ((__nv_bfloat162*)ldst)[1] = __nv_bfloat162(
        __float2bfloat16(v.z - __bfloat162float(h2)),
        __float2bfloat16(v.w - __bfloat162float(h3)));
}

// ---------------- split-precision convert kernels ----------------
__global__ __launch_bounds__(256)
void split_k(const float* __restrict__ s, __nv_bfloat16* __restrict__ h,
             __nv_bfloat16* __restrict__ l, int n4)
{
    int i = blockIdx.x * 256 + threadIdx.x;
    if (i >= n4) return;
    float4 v = ((const float4*)s)[i];
    split4(v, h + i * 4, l + i * 4);
}

// Transpose + split the 5 weight matrices: wt[z][n][k] = W_z[k][n]
__global__ __launch_bounds__(256)
void wsplit_k(const float* __restrict__ W0, const float* __restrict__ W1,
              const float* __restrict__ W2, const float* __restrict__ W3,
              const float* __restrict__ W4,
              __nv_bfloat16* __restrict__ th, __nv_bfloat16* __restrict__ tl)
{
    const float* W;
    switch (blockIdx.z) {
        case 0: W = W0; break;
        case 1: W = W1; break;
        case 2: W = W2; break;
        case 3: W = W3; break;
        default: W = W4; break;
    }
    __shared__ float t[32][33];
    int tx = threadIdx.x & 31, ty = threadIdx.x >> 5;
    int n0 = blockIdx.x * 32, k0 = blockIdx.y * 32;
#pragma unroll
    for (int ph = 0; ph < 4; ph++)
        t[ty + ph * 8][tx] = W[(size_t)(k0 + ty + ph * 8) * ND + n0 + tx];
    __syncthreads();
    size_t base = (size_t)blockIdx.z * ND * ND;
#pragma unroll
    for (int ph = 0; ph < 4; ph++) {
        int n = n0 + ty + ph * 8, k = k0 + tx;
        float v = t[tx][ty + ph * 8];
        __nv_bfloat16 hh = __float2bfloat16(v);
        __nv_bfloat16 ll = __float2bfloat16(v - __bfloat162float(hh));
        th[base + (size_t)n * ND + k] = hh;
        tl[base + (size_t)n * ND + k] = ll;
    }
}

// ---------------------------------------------------------------------------
// mma.sync split-bf16 GEMM (proven in R11).
// ---------------------------------------------------------------------------
#define MT_AH 0
#define MT_AL 10240
#define MT_BH 20480
#define MT_BL 30720
#define MT_BUF 40960
#define MT_SMEM 81920

template<int MODE>
__device__ __forceinline__
void mmagemm_body(const __nv_bfloat16* __restrict__ Ah, const __nv_bfloat16* __restrict__ Al,
                  const __nv_bfloat16* __restrict__ Bh, const __nv_bfloat16* __restrict__ Bl,
                  const float* __restrict__ bias, float* __restrict__ C,
                  int M, int row0, int col0, char* smraw)
{
    const int tid  = threadIdx.x;
    const int lane = tid & 31;
    const int wid  = tid >> 5;
    const int warp_m = wid >> 2;
    const int warp_n = wid & 3;
    const uint32_t smb = smem_u32(smraw);

    const int ldrow = tid >> 1;
    const int ldc8  = (tid & 1) * 16;
    const bool okA  = (row0 + ldrow) < M;
    const size_t agoff = (size_t)(row0 + ldrow) * ND;
    const size_t bgoff = (size_t)(col0 + ldrow) * ND;
    const uint32_t srow = (uint32_t)ldrow * 40;
    const int szA = okA ? 16 : 0;

    float acc[4][4][4];
#pragma unroll
    for (int mi = 0; mi < 4; mi++)
#pragma unroll
        for (int ni = 0; ni < 4; ni++)
#pragma unroll
            for (int e = 0; e < 4; e++) acc[mi][ni][e] = 0.f;

    const int a_row = warp_m * 64 + (lane & 7) + ((lane >> 3) & 1) * 8;
    const int b_row = warp_n * 32 + (lane & 7) + ((lane >> 3) & 1) * 8;
    const int lm_k  = (lane >> 4) * 8;

    auto load_tile = [&](int k0, int buf) {
        uint32_t sb = smb + buf * MT_BUF;
#pragma unroll
        for (int c = 0; c < 2; c++) {
            int col = ldc8 + c * 8;
            uint32_t so = (srow + col) * 2;
            cpa16(sb + MT_AH + so, Ah + agoff + k0 + col, szA);
            cpa16(sb + MT_AL + so, Al + agoff + k0 + col, szA);
            cpa16(sb + MT_BH + so, Bh + bgoff + k0 + col, 16);
            cpa16(sb + MT_BL + so, Bl + bgoff + k0 + col, 16);
        }
    };

    load_tile(0, 0);
    cpa_commit();

    int buf = 0;
    for (int it = 0; it < 16; it++) {
        cpa_wait0();
        __syncthreads();
        if (it < 15) {
            load_tile((it + 1) * 32, buf ^ 1);
            cpa_commit();
        }
        const uint32_t sb = smb + buf * MT_BUF;
#pragma unroll
        for (int ks = 0; ks < 2; ks++) {
            const int kofs = ks * 16 + lm_k;
            uint32_t bh[2][4], bl[2][4];
#pragma unroll
            for (int p = 0; p < 2; p++) {
                uint32_t off = (uint32_t)((b_row + p * 16) * 40 + kofs) * 2;
                LDSM4(bh[p], sb + MT_BH + off);
                LDSM4(bl[p], sb + MT_BL + off);
            }
#pragma unroll
            for (int mi = 0; mi < 4; mi++) {
                uint32_t ah[4], al[4];
                uint32_t off = (uint32_t)((a_row + mi * 16) * 40 + kofs) * 2;
                LDSM4(ah, sb + MT_AH + off);
                LDSM4(al, sb + MT_AL + off);
#pragma unroll
                for (int ni = 0; ni < 4; ni++) {
                    const int p = ni >> 1, hi = ni & 1;
                    MMA16816(acc[mi][ni], ah, bh[p][hi], bh[p][hi + 2]);
                    MMA16816(acc[mi][ni], ah, bl[p][hi], bl[p][hi + 2]);
                    MMA16816(acc[mi][ni], al, bh[p][hi], bh[p][hi + 2]);
                }
            }
        }
        buf ^= 1;
    }

#pragma unroll
    for (int mi = 0; mi < 4; mi++) {
        const int r0 = row0 + warp_m * 64 + mi * 16 + (lane >> 2);
#pragma unroll
        for (int ni = 0; ni < 4; ni++) {
            const int col = col0 + warp_n * 32 + ni * 8 + (lane & 3) * 2;
            const float b0 = bias ? bias[col] : 0.f;
            const float b1 = bias ? bias[col + 1] : 0.f;
#pragma unroll
            for (int half = 0; half < 2; half++) {
                const int m = r0 + half * 8;
                if (m >= M) continue;
                float2 o;
                o.x = acc[mi][ni][half * 2 + 0] + b0;
                o.y = acc[mi][ni][half * 2 + 1] + b1;
                if (MODE == 0) {
                    *(float2*)(C + (size_t)m * ND + col) = o;
                } else if (MODE == 1) {
                    int b = m >> 10, t = m & 1023;
                    int h = col >> 6, d = col & 63;
                    *(float2*)(C + ((size_t)((b << 3) + h) * NT + t) * NDH + d) = o;
                } else {
                    int h = col >> 6, d = col & 63;
                    *(float2*)(C + ((size_t)h * NSPOS + m) * NDH + d) = o;
                }
            }
        }
    }
}

template<int MODE>
__global__ __launch_bounds__(256, 2)
void mmagemm_k(const __nv_bfloat16* __restrict__ Ah, const __nv_bfloat16* __restrict__ Al,
               const __nv_bfloat16* __restrict__ Bh, const __nv_bfloat16* __restrict__ Bl,
               const float* __restrict__ bias, float* __restrict__ C, int M)
{
    extern __shared__ char smraw[];
    mmagemm_body<MODE>(Ah, Al, Bh, Bl, bias, C, M,
                       blockIdx.x << 7, blockIdx.y << 7, smraw);
}

__global__ __launch_bounds__(256, 2)
void mmagemm_fused_k(const __nv_bfloat16* __restrict__ xh, const __nv_bfloat16* __restrict__ xl,
                     const __nv_bfloat16* __restrict__ peh, const __nv_bfloat16* __restrict__ pel,
                     const __nv_bfloat16* __restrict__ wth, const __nv_bfloat16* __restrict__ wtl,
                     const float* __restrict__ bq, const float* __restrict__ bk,
                     const float* __restrict__ bv,
                     float* __restrict__ Cq, float* __restrict__ Ck,
                     float* __restrict__ Cv, float* __restrict__ Cp)
{
    extern __shared__ char smraw[];
    const int z = blockIdx.z;
    const size_t WSZ = (size_t)ND * ND;
    if (z == 3) {
        if (blockIdx.x >= 16) return;
        mmagemm_body<2>(peh, pel, wth + 3 * WSZ, wtl + 3 * WSZ, nullptr, Cp, NSPOS,
                        blockIdx.x << 7, blockIdx.y << 7, smraw);
    } else {
        const float* bias = (z == 0) ? bq : (z == 1) ? bk : bv;
        float* C = (z == 0) ? Cq : (z == 1) ? Ck : Cv;
        mmagemm_body<1>(xh, xl, wth + z * WSZ, wtl + z * WSZ, bias, C, NB * NT,
                        blockIdx.x << 7, blockIdx.y << 7, smraw);
    }
}

// ---------------------------------------------------------------------------
// attn_k v4: 64q x 64k tiles, 256 thr. Content score, pos score (128-col smem
// ring) AND AV all on tensor pipe (split-bf16 mma.sync). P split to bf16 h/l;
// V staged transposed (Vt[d][c]) so the AV MMA uses normal ldmatrix.
// O accumulated in MMA fragments; flash rescale via salpha[] broadcast.
// ---------------------------------------------------------------------------
#define AT_QUH 0
#define AT_QUL 9216
#define AT_QVH 18432
#define AT_QVL 27648
#define AT_KH  36864
#define AT_KL  46080
#define AT_PEH 55296
#define AT_PEL 64512
#define AT_VTH 73728
#define AT_VTL 82944
#define AT_PRH 92160
#define AT_PRL 101376
#define AT_RING 110592   // f32 [64][132]
#define AT_SS   144384   // f32 [64][66]
#define AT_ALPHA 161280  // f32 [64]
#define AT_SL    161536  // f32 [64]
#define AT_SMEM  161792

__global__ __launch_bounds__(256)
void attn_k(const float* __restrict__ q, const float* __restrict__ k,
            const float* __restrict__ v, const float* __restrict__ p,
            const float* __restrict__ pbu, const float* __restrict__ pbv,
            __nv_bfloat16* __restrict__ aoh, __nv_bfloat16* __restrict__ aol)
{
    extern __shared__ char smraw[];
    const uint32_t smb = smem_u32(smraw);
    __nv_bfloat16* sm16 = (__nv_bfloat16*)smraw;
    float* ring   = (float*)(smraw + AT_RING);
    float* sS     = (float*)(smraw + AT_SS);
    float* salpha = (float*)(smraw + AT_ALPHA);
    float* sl     = (float*)(smraw + AT_SL);
    __nv_bfloat16* prh = sm16 + AT_PRH / 2;
    __nv_bfloat16* prl = sm16 + AT_PRL / 2;
    __nv_bfloat16* vth = sm16 + AT_VTH / 2;
    __nv_bfloat16* vtl = sm16 + AT_VTL / 2;

    const int tid = threadIdx.x;
    const int lane = tid & 31, wid = tid >> 5;
    const int warp_m = wid & 3, warp_n = wid >> 2;
    const int tx = tid >> 4, ty = tid & 15;
    const int bx = blockIdx.x;
    const int t0 = (bx & 15) << 6;
    const int bh = bx >> 4;
    const int h = bh & 7, b = bh >> 3;

    const float* qb = q + ((size_t)bh * NT + t0) * NDH;
    const float* kb = k + (size_t)bh * NT * NDH;
    const float* vb = v + (size_t)bh * NT * NDH;
    const float* pb = p + (size_t)h * NSPOS * NDH;
    const int pj0 = 960 - t0;

    const int a_row = warp_m * 16 + (lane & 7) + 8 * ((lane >> 3) & 1);
    const int b_row = warp_n * 32 + (lane & 7) + 8 * ((lane >> 3) & 1);
    const int lm_k  = (lane >> 4) * 8;
    const int fs_row = warp_m * 16 + (lane >> 2);
    const int fs_col = warp_n * 32 + (lane & 3) * 2;

    const int ldr = tid >> 2;           // 0..63
    const int ldd = (tid & 3) << 4;     // 0,16,32,48 (float4 staging)
    const int vdl = tid & 3;            // Vt staging d-lane

    // ---- stage Qu/Qv (once) ----
#pragma unroll
    for (int c = 0; c < 4; c++) {
        int d = ldd + c * 4;
        float4 qq = *(const float4*)(qb + ldr * NDH + d);
        float4 uu = *(const float4*)(pbu + h * NDH + d);
        float4 vv = *(const float4*)(pbv + h * NDH + d);
        float4 qu = make_float4(qq.x+uu.x, qq.y+uu.y, qq.z+uu.z, qq.w+uu.w);
        float4 qv = make_float4(qq.x+vv.x, qq.y+vv.y, qq.z+vv.z, qq.w+vv.w);
        int ofs = ldr * 72 + d;
        split4(qu, sm16 + AT_QUH/2 + ofs, sm16 + AT_QUL/2 + ofs);
        split4(qv, sm16 + AT_QVH/2 + ofs, sm16 + AT_QVL/2 + ofs);
    }

    auto stage_p = [&](int blk) {
        int j = pj0 + blk * 64 + ldr;
        j = j > 2046 ? 2046 : j;
#pragma unroll
        for (int c = 0; c < 4; c++) {
            int d = ldd + c * 4;
            float4 pv = *(const float4*)(pb + (size_t)j * NDH + d);
            int ofs = ldr * 72 + d;
            split4(pv, sm16 + AT_PEH/2 + ofs, sm16 + AT_PEL/2 + ofs);
        }
    };
    auto stage_kv = [&](int n) {
        const float* krow = kb + (size_t)(n * 64 + ldr) * NDH;
#pragma unroll
        for (int c = 0; c < 4; c++) {
            int d = ldd + c * 4;
            float4 kk = *(const float4*)(krow + d);
            int ofs = ldr * 72 + d;
            split4(kk, sm16 + AT_KH/2 + ofs, sm16 + AT_KL/2 + ofs);
        }
        // V transposed: Vt[d][c], c = ldr, d = vdl + 4m  (bank-conflict-free)
        const float* vrow = vb + (size_t)(n * 64 + ldr) * NDH;
#pragma unroll
        for (int m = 0; m < 16; m++) {
            int d = vdl + 4 * m;
            float vv = vrow[d];
            __nv_bfloat16 hh = __float2bfloat16(vv);
            vth[d * 72 + ldr] = hh;
            vtl[d * 72 + ldr] = __float2bfloat16(vv - __bfloat162float(hh));
        }
    };

    // generic 64x64x64 split MMA (3 products) into fresh cc
    auto mma_tile = [&](uint32_t aH, uint32_t aL, uint32_t bH, uint32_t bL,
                        float cc[4][4]) {
#pragma unroll
        for (int ni = 0; ni < 4; ni++)
#pragma unroll
            for (int e = 0; e < 4; e++) cc[ni][e] = 0.f;
#pragma unroll
        for (int ks = 0; ks < 4; ks++) {
            const int kofs = ks * 16 + lm_k;
            uint32_t ah[4], al[4], bh2[2][4], bl2[2][4];
            LDSM4(ah, aH + (uint32_t)(a_row * 72 + kofs) * 2);
            LDSM4(al, aL + (uint32_t)(a_row * 72 + kofs) * 2);
#pragma unroll
            for (int p2 = 0; p2 < 2; p2++) {
                uint32_t off = (uint32_t)((b_row + p2 * 16) * 72 + kofs) * 2;
                LDSM4(bh2[p2], bH + off);
                LDSM4(bl2[p2], bL + off);
            }
#pragma unroll
            for (int ni = 0; ni < 4; ni++) {
                const int p2 = ni >> 1, hi = ni & 1;
                MMA16816(cc[ni], ah, bh2[p2][hi], bh2[p2][hi + 2]);
                MMA16816(cc[ni], ah, bl2[p2][hi], bl2[p2][hi + 2]);
                MMA16816(cc[ni], al, bh2[p2][hi], bh2[p2][hi + 2]);
            }
        }
    };

    auto pos_mma = [&](int blk) {
        float cc[4][4];
        mma_tile(smb + AT_QVH, smb + AT_QVL, smb + AT_PEH, smb + AT_PEL, cc);
        const int slot = (blk & 1) << 6;
#pragma unroll
        for (int ni = 0; ni < 4; ni++) {
            int col = slot + fs_col + ni * 8;
            *(float2*)(ring + fs_row * 132 + col)       = make_float2(cc[ni][0], cc[ni][1]);
            *(float2*)(ring + (fs_row + 8) * 132 + col) = make_float2(cc[ni][2], cc[ni][3]);
        }
    };

    // ---- preamble ----
    stage_p(0);
    __syncthreads();
    pos_mma(0);
    __syncthreads();
    stage_p(1);
    stage_kv(0);
    __syncthreads();
    pos_mma(1);

    float acc_o[4][4];
#pragma unroll
    for (int ni = 0; ni < 4; ni++)
#pragma unroll
        for (int e = 0; e < 4; e++) acc_o[ni][e] = 0.f;
    float m_i[4], l_i[4];
#pragma unroll
    for (int i = 0; i < 4; i++) { m_i[i] = -3.0e38f; l_i[i] = 0.f; }

    for (int n = 0; n < 16; n++) {
        // ---- content score MMA -> sS ----
        {
            float cc[4][4];
            mma_tile(smb + AT_QUH, smb + AT_QUL, smb + AT_KH, smb + AT_KL, cc);
#pragma unroll
            for (int ni = 0; ni < 4; ni++) {
                int col = fs_col + ni * 8;
                *(float2*)(sS + fs_row * 66 + col)       = make_float2(cc[ni][0], cc[ni][1]);
                *(float2*)(sS + (fs_row + 8) * 66 + col) = make_float2(cc[ni][2], cc[ni][3]);
            }
        }
        __syncthreads();

        // ---- softmax: write split-bf16 P + alpha ----
        const int pw = (n << 6) + 63;
#pragma unroll
        for (int i = 0; i < 4; i++) {
            const int r = tx + (i << 4);
            float s[4];
            float mt = -3.0e38f;
#pragma unroll
            for (int j = 0; j < 4; j++) {
                const int c = ty + (j << 4);
                const int rc = (pw + c - r) & 127;
                s[j] = (sS[r * 66 + c] + ring[r * 132 + rc]) * ATT_SCALE;
                mt = fmaxf(mt, s[j]);
            }
#pragma unroll
            for (int off = 8; off >= 1; off >>= 1)
                mt = fmaxf(mt, __shfl_xor_sync(0xffffffffu, mt, off));
            float mn = fmaxf(m_i[i], mt);
            float alpha = __expf(m_i[i] - mn);
            m_i[i] = mn;
            float rs = 0.f;
#pragma unroll
            for (int j = 0; j < 4; j++) {
                float ev = __expf(s[j] - mn);
                s[j] = ev;
                rs += ev;
            }
#pragma unroll
            for (int off = 8; off >= 1; off >>= 1)
                rs += __shfl_xor_sync(0xffffffffu, rs, off);
            l_i[i] = l_i[i] * alpha + rs;
            if (ty == 0) salpha[r] = alpha;
#pragma unroll
            for (int j = 0; j < 4; j++) {
                const int c = ty + (j << 4);
                __nv_bfloat16 hh = __float2bfloat16(s[j]);
                prh[r * 72 + c] = hh;
                prl[r * 72 + c] = __float2bfloat16(s[j] - __bfloat162float(hh));
            }
        }
        __syncthreads();

        // ---- AV MMA: rescale acc_o by alpha, accumulate P @ Vt ----
        {
            float a_lo = salpha[fs_row], a_hi = salpha[fs_row + 8];
#pragma unroll
            for (int ni = 0; ni < 4; ni++) {
                acc_o[ni][0] *= a_lo; acc_o[ni][1] *= a_lo;
                acc_o[ni][2] *= a_hi; acc_o[ni][3] *= a_hi;
            }
#pragma unroll
            for (int ks = 0; ks < 4; ks++) {
                const int kofs = ks * 16 + lm_k;
                uint32_t ah[4], al[4], bh2[2][4], bl2[2][4];
                LDSM4(ah, smb + AT_PRH + (uint32_t)(a_row * 72 + kofs) * 2);
                LDSM4(al, smb + AT_PRL + (uint32_t)(a_row * 72 + kofs) * 2);
#pragma unroll
                for (int p2 = 0; p2 < 2; p2++) {
                    uint32_t off = (uint32_t)((b_row + p2 * 16) * 72 + kofs) * 2;
                    LDSM4(bh2[p2], smb + AT_VTH + off);
                    LDSM4(bl2[p2], smb + AT_VTL + off);
                }
#pragma unroll
                for (int ni = 0; ni < 4; ni++) {
                    const int p2 = ni >> 1, hi = ni & 1;
                    MMA16816(acc_o[ni], ah, bh2[p2][hi], bh2[p2][hi + 2]);
                    MMA16816(acc_o[ni], ah, bl2[p2][hi], bl2[p2][hi + 2]);
                    MMA16816(acc_o[ni], al, bh2[p2][hi], bh2[p2][hi + 2]);
                }
            }
        }
        __syncthreads();

        // ---- stage next K/V and p-block; pos MMA appends ring ----
        if (n < 15) stage_kv(n + 1);
        const bool havep = (n + 2) <= 16;
        if (havep) stage_p(n + 2);
        __syncthreads();
        if (havep) pos_mma(n + 2);
    }

    // ---- epilogue ----
    if (ty == 0) {
#pragma unroll
        for (int i = 0; i < 4; i++) sl[tx + (i << 4)] = l_i[i];
    }
    __syncthreads();
#pragma unroll
    for (int half = 0; half < 2; half++) {
        const int row = fs_row + half * 8;
        const float inv = 1.f / sl[row];
        size_t base = ((size_t)b * NT + t0 + row) * ND + h * NDH;
#pragma unroll
        for (int ni = 0; ni < 4; ni++) {
            const int col = fs_col + ni * 8;
            float o0 = acc_o[ni][half * 2 + 0] * inv;
            float o1 = acc_o[ni][half * 2 + 1] * inv;
            __nv_bfloat16 h0 = __float2bfloat16(o0);
            __nv_bfloat16 h1 = __float2bfloat16(o1);
            *(__nv_bfloat162*)(aoh + base + col) = __nv_bfloat162(h0, h1);
            *(__nv_bfloat162*)(aol + base + col) = __nv_bfloat162(
                __float2bfloat16(o0 - __bfloat162float(h0)),
                __float2bfloat16(o1 - __bfloat162float(h1)));
        }
    }
}

// ---------------------------------------------------------------------------
extern "C" void kernel_launch(void* const* d_in, const int* in_sizes, int n_in,
                              void* d_out, int out_size)
{
    const float* x    = (const float*)d_in[0];
    const float* pe   = (const float*)d_in[1];
    const float* Wq   = (const float*)d_in[2];
    const float* bq   = (const float*)d_in[3];
    const float* Wk   = (const float*)d_in[4];
    const float* bk   = (const float*)d_in[5];
    const float* Wv   = (const float*)d_in[6];
    const float* bv   = (const float*)d_in[7];
    const float* Wpos = (const float*)d_in[8];
    const float* pbu  = (const float*)d_in[9];
    const float* pbv  = (const float*)d_in[10];
    const float* Wo   = (const float*)d_in[11];
    const float* bo   = (const float*)d_in[12];
    float* out = (float*)d_out;

    float *qp, *kp, *vp_, *pp;
    cudaGetSymbolAddress((void**)&qp,  g_q);
    cudaGetSymbolAddress((void**)&kp,  g_k);
    cudaGetSymbolAddress((void**)&vp_, g_v);
    cudaGetSymbolAddress((void**)&pp,  g_p);
    __nv_bfloat16 *xh, *xl, *peh, *pel, *wth, *wtl, *aoh, *aol;
    cudaGetSymbolAddress((void**)&xh,  g_xh);
    cudaGetSymbolAddress((void**)&xl,  g_xl);
    cudaGetSymbolAddress((void**)&peh, g_peh);
    cudaGetSymbolAddress((void**)&pel, g_pel);
    cudaGetSymbolAddress((void**)&wth, g_wth);
    cudaGetSymbolAddress((void**)&wtl, g_wtl);
    cudaGetSymbolAddress((void**)&aoh, g_aoh);
    cudaGetSymbolAddress((void**)&aol, g_aol);

    cudaFuncSetAttribute(mmagemm_fused_k, cudaFuncAttributeMaxDynamicSharedMemorySize, MT_SMEM);
    cudaFuncSetAttribute(mmagemm_k<0>,    cudaFuncAttributeMaxDynamicSharedMemorySize, MT_SMEM);
    cudaFuncSetAttribute(attn_k,          cudaFuncAttributeMaxDynamicSharedMemorySize, AT_SMEM);

    const size_t WSZ = (size_t)ND * ND;
    dim3 blk(256);

    split_k<<<(NB*NT*ND/4 + 255)/256, blk>>>(x,  xh,  xl,  NB*NT*ND/4);
    split_k<<<(NSPOS*ND/4 + 255)/256, blk>>>(pe, peh, pel, NSPOS*ND/4);
    wsplit_k<<<dim3(16, 16, 5), blk>>>(Wq, Wk, Wv, Wpos, Wo, wth, wtl);

    mmagemm_fused_k<<<dim3(64, 4, 4), blk, MT_SMEM>>>(xh, xl, peh, pel, wth, wtl,
                                                      bq, bk, bv, qp, kp, vp_, pp);
    attn_k<<<NB * NH * (NT / 64), blk, AT_SMEM>>>(qp, kp, vp_, pp, pbu, pbv, aoh, aol);
    mmagemm_k<0><<<dim3(64, 4), blk, MT_SMEM>>>(aoh, aol, wth + 4*WSZ, wtl + 4*WSZ,
                                                bo, out, NB * NT);
}